// round 9
// baseline (speedup 1.0000x reference)
#include <cuda_runtime.h>
#include <math.h>

// Problem constants (fixed shapes per reference)
#define NN   2049          // max_seq_len
#define NOUT 2048          // output rows/cols = N-1
#define BB   16            // batch
// pos_w has 2*NN-1 = 4097 entries, ts_w has 129 entries.

// Device scratch (no allocations allowed in kernel_launch)
__device__ int4 g_lut[128];          // {thr_bits, vlo_bits, vhi_bits, 0} per quarter-octave cell
__device__ int  g_ts32[BB * NN];     // timestamps normalized to int32

// ---------------------------------------------------------------------------
// Genuine libdevice logf (linked from libdevice.bc; immune to fast-math's
// logf->__logf substitution). Proven bit-equal to correctly-rounded f32 log
// at every division-decision integer — the faithful-log class.
// ---------------------------------------------------------------------------
extern "C" __device__ float __nv_logf(float);

// ---------------------------------------------------------------------------
// KEY CHANGE (round 9): XLA's algebraic simplifier rewrites
//     divide(log(x), 0.301f)  ->  multiply(log(x), constant(1/0.301f))
// by default (HLO-level, both CPU and GPU backends). The reciprocal constant
// is folded in f32 (HloEvaluator: 1.0f / 0.301f, round-to-nearest). So the
// reference's bucket is floor( log(x) * rn(1/0.301f) ), NOT floor(log/0.301).
// The mul's systematic ~1-ulp deviation from true division is exactly the
// ~2-5e-6 q-offset needed to flip the ~10 decision integers observed.
// ---------------------------------------------------------------------------
__device__ __forceinline__ float recip_0301() {
    return __fdiv_rn(1.0f, 0.301f);          // f32 constant-folded reciprocal
}

__device__ __forceinline__ int bucket_ref(int v) {
    float r = __nv_logf((float)v);           // faithful f32 log
    float q = __fmul_rn(r, recip_0301());    // XLA's multiply-by-reciprocal
    return (int)floorf(q);
}

// First INTEGER v in [1, 1e6] with bucket(v) >= k (monotone at integer
// granularity); +inf bits if never reached. Searching integers makes the LUT
// exact at every realizable |dt| and immune to sub-integer wiggle.
__device__ __forceinline__ int first_int_bits_ge(int k) {
    int lo = 1;
    int hi = 1000000;
    if (bucket_ref(hi) < k) return 0x7F800000;
    while (lo < hi) {
        int mid = lo + ((hi - lo) >> 1);
        if (bucket_ref(mid) >= k) hi = mid; else lo = mid + 1;
    }
    return __float_as_int((float)lo);
}

// Build bucket thresholds (float bits of the first integer with bucket >= k)
// and the 128-cell LUT. Cell c covers float bits [ (c+508)<<21, (c+509)<<21 )
// — a quarter octave, so at most ONE bucket boundary per cell (boundaries are
// ~0.434 octaves apart).
__global__ void k_build_lut(const float* __restrict__ ts_w) {
    __shared__ int Tb[81];
    int tid = threadIdx.x;
    if (tid <= 80) Tb[tid] = 0x7F800000;     // +inf bits == "no threshold"
    __syncthreads();

    if (tid >= 1 && tid < 80) {
        Tb[tid] = first_int_bits_ge(tid);
    }
    __syncthreads();

    if (tid < 128) {
        int cellbase = (tid + 508) << 21;
        int cellend  = cellbase + (1 << 21);
        int blo = 0;
        #pragma unroll 1
        for (int k = 1; k < 80; ++k) blo += (Tb[k] <= cellbase) ? 1 : 0;
        int thr = 0x7F800000;
        if (blo + 1 < 80 && Tb[blo + 1] < cellend) thr = Tb[blo + 1];
        int kv0 = min(blo, 128);
        int kv1 = min(blo + 1, 128);
        int4 e;
        e.x = thr;
        e.y = __float_as_int(ts_w[kv0]);
        e.z = __float_as_int(ts_w[kv1]);
        e.w = 0;
        g_lut[tid] = e;
    }
}

// ---------------------------------------------------------------------------
// Dtype-robust timestamp normalization (reference may hand us int64 or int32;
// values < 1e6, so int64 high words are all zero — detect and convert).
// ---------------------------------------------------------------------------
__global__ void __launch_bounds__(1024)
k_cvt_ts_any(const int* __restrict__ ts_raw) {
    __shared__ int s_flag;
    const int tid = threadIdx.x;
    if (tid == 0) s_flag = 0;
    __syncthreads();

    int local = 0;
    for (int idx = tid; idx < (BB * NN) / 2; idx += 1024)
        local |= ts_raw[2 * idx + 1];
    if (local) atomicOr(&s_flag, 1);
    __syncthreads();

    const bool is64 = (s_flag == 0);
    if (is64) {
        for (int idx = tid; idx < BB * NN; idx += 1024)
            g_ts32[idx] = ts_raw[2 * idx];
    } else {
        for (int idx = tid; idx < BB * NN; idx += 1024)
            g_ts32[idx] = ts_raw[idx];
    }
}

// ---------------------------------------------------------------------------
// Main kernel. Block = 16 rows of one batch, rows i = base_i + 4*r so all rows
// share (i mod 4) -> pos_w slice staged in shared with alignment-preserving
// shift, giving aligned LDS.128 for the Toeplitz vector.
// out[b,i,j] = pos_w[j-i+2048] + ts_w[bucket(ts[b,i+1]-ts[b,j])]
// ---------------------------------------------------------------------------
__device__ __forceinline__ float ts_bias(int tsi1, int tsj, const int4* lut) {
    int dt = tsi1 - tsj;
    int x  = abs(dt);
    x      = max(x, 1);
    float xf = (float)x;                     // exact (x < 2^24)
    int bx   = __float_as_int(xf);
    int idx  = (bx >> 21) - 508;
    int4 L   = lut[idx];
    return __int_as_float(bx >= L.x ? L.z : L.y);
}

__global__ void __launch_bounds__(256)
k_main(const float* __restrict__ pos_w, float* __restrict__ out) {
    __shared__ __align__(16) float s_pos[2112];
    __shared__ __align__(16) int   s_ts[2052];
    __shared__ int4 s_lut[128];

    const int tid = threadIdx.x;
    const int blk = blockIdx.x;
    const int b   = blk >> 7;                // 128 blocks per batch
    const int rb  = blk & 127;
    const int a   = rb & 3;                  // residue i mod 4
    const int tb  = rb >> 2;                 // 0..31
    const int base_i  = a + (tb << 6);       // rows: base_i + 4r, r in [0,16)
    const int s_start = 2048 - base_i - 60;  // pos_w staging origin (>= 1)

    for (int u = tid; u < 2108; u += 256) s_pos[u] = pos_w[s_start + u];
    for (int u = tid; u < 2049; u += 256) s_ts[u] = g_ts32[b * NN + u];
    if (tid < 128) s_lut[tid] = g_lut[tid];
    __syncthreads();

    const int j0 = tid << 2;                 // 0..1020, second half at +1024
    const int4 tsA = *(const int4*)&s_ts[j0];
    const int4 tsB = *(const int4*)&s_ts[j0 + 1024];

    #pragma unroll
    for (int r = 0; r < 16; ++r) {
        const int i    = base_i + (r << 2);
        const int tsi1 = s_ts[i + 1];
        float* orow = out + (((size_t)(b * NOUT + i)) << 11);
        const int poff = j0 + 60 - (r << 2); // multiple of 4 -> aligned LDS.128

        {
            float4 pw = *(const float4*)&s_pos[poff];
            float4 o;
            o.x = ts_bias(tsi1, tsA.x, s_lut) + pw.x;
            o.y = ts_bias(tsi1, tsA.y, s_lut) + pw.y;
            o.z = ts_bias(tsi1, tsA.z, s_lut) + pw.z;
            o.w = ts_bias(tsi1, tsA.w, s_lut) + pw.w;
            *(float4*)&orow[j0] = o;
        }
        {
            float4 pw = *(const float4*)&s_pos[poff + 1024];
            float4 o;
            o.x = ts_bias(tsi1, tsB.x, s_lut) + pw.x;
            o.y = ts_bias(tsi1, tsB.y, s_lut) + pw.y;
            o.z = ts_bias(tsi1, tsB.z, s_lut) + pw.z;
            o.w = ts_bias(tsi1, tsB.w, s_lut) + pw.w;
            *(float4*)&orow[j0 + 1024] = o;
        }
    }
}

extern "C" void kernel_launch(void* const* d_in, const int* in_sizes, int n_in,
                              void* d_out, int out_size) {
    // Identify inputs by element count, not position (defensive).
    const void*  ts_raw = d_in[0];
    const float* posw   = (const float*)d_in[1];
    const float* tsw    = (const float*)d_in[2];
    for (int k = 0; k < n_in; ++k) {
        if (in_sizes[k] == BB * NN)         ts_raw = d_in[k];
        else if (in_sizes[k] == 2 * NN - 1) posw   = (const float*)d_in[k];
        else if (in_sizes[k] == 129)        tsw    = (const float*)d_in[k];
    }
    float* out = (float*)d_out;              // (16, 2048, 2048) f32

    k_build_lut<<<1, 128>>>(tsw);
    k_cvt_ts_any<<<1, 1024>>>((const int*)ts_raw);
    k_main<<<BB * 128, 256>>>(posw, out);
}

// round 11
// speedup vs baseline: 1.2954x; 1.2954x over previous
#include <cuda_runtime.h>
#include <math.h>

// Problem constants (fixed shapes per reference)
#define NN   2049          // max_seq_len
#define NOUT 2048          // output rows/cols = N-1
#define BB   16            // batch
// pos_w has 2*NN-1 = 4097 entries, ts_w has 129 entries.

// Device scratch (no allocations allowed in kernel_launch)
__device__ int4 g_lut[128];          // {thr_bits, vlo_bits, vhi_bits, 0} per quarter-octave cell
__device__ int  g_ts32[BB * NN];     // timestamps normalized to int32

// ---------------------------------------------------------------------------
// Genuine libdevice logf (linked from libdevice.bc; immune to fast-math's
// logf->__logf substitution).
// ---------------------------------------------------------------------------
extern "C" __device__ float __nv_logf(float);

// Reference bucketization (verified bit-exact vs the jax reference in R9):
// XLA's algebraic simplifier rewrites divide(log(x), 0.301f) into
// multiply(log(x), rn(1/0.301f)); reciprocal folded in f32.
__device__ __forceinline__ int bucket_ref(int v) {
    float r = __nv_logf((float)v);
    float q = __fmul_rn(r, __fdiv_rn(1.0f, 0.301f));
    return (int)floorf(q);
}

// First INTEGER v in [1, 1e6] with bucket(v) >= k; +inf bits if never reached.
__device__ __forceinline__ int first_int_bits_ge(int k) {
    int lo = 1;
    int hi = 1000000;
    if (bucket_ref(hi) < k) return 0x7F800000;
    while (lo < hi) {
        int mid = lo + ((hi - lo) >> 1);
        if (bucket_ref(mid) >= k) hi = mid; else lo = mid + 1;
    }
    return __float_as_int((float)lo);
}

// ---------------------------------------------------------------------------
// Fused prologue: ONE launch.
//   blocks 0..15 : normalize timestamps of batch b (dtype-robust int64/int32)
//   block  16    : build the 128-cell threshold LUT
// Detection reads only pair indices < 16392 (first 32784 int words), which
// are inside the buffer under BOTH dtype interpretations.
// ---------------------------------------------------------------------------
__global__ void __launch_bounds__(256)
k_prep(const int* __restrict__ ts_raw, const float* __restrict__ ts_w) {
    const int tid = threadIdx.x;
    const int blk = blockIdx.x;

    if (blk < BB) {
        // --- dtype detection on this block's private safe slice ---
        __shared__ int s_flag;
        if (tid == 0) s_flag = 0;
        __syncthreads();
        int local = 0;
        const int p0 = blk * 1024;           // pairs [p0, p0+1024) all < 16392
        for (int p = p0 + tid; p < p0 + 1024; p += 256)
            local |= ts_raw[2 * p + 1];
        if (local) atomicOr(&s_flag, 1);
        __syncthreads();

        const bool is64 = (s_flag == 0);
        const int base = blk * NN;
        if (is64) {
            for (int u = tid; u < NN; u += 256)
                g_ts32[base + u] = ts_raw[2 * (base + u)];
        } else {
            for (int u = tid; u < NN; u += 256)
                g_ts32[base + u] = ts_raw[base + u];
        }
    } else {
        // --- LUT build ---
        __shared__ int Tb[81];
        if (tid <= 80) Tb[tid] = 0x7F800000;
        __syncthreads();
        if (tid >= 1 && tid < 80) Tb[tid] = first_int_bits_ge(tid);
        __syncthreads();

        if (tid < 128) {
            int cellbase = (tid + 508) << 21;
            int cellend  = cellbase + (1 << 21);
            int blo = 0;
            #pragma unroll 1
            for (int k = 1; k < 80; ++k) blo += (Tb[k] <= cellbase) ? 1 : 0;
            int thr = 0x7F800000;
            if (blo + 1 < 80 && Tb[blo + 1] < cellend) thr = Tb[blo + 1];
            int kv0 = min(blo, 128);
            int kv1 = min(blo + 1, 128);
            int4 e;
            e.x = thr;
            e.y = __float_as_int(ts_w[kv0]);
            e.z = __float_as_int(ts_w[kv1]);
            e.w = 0;
            g_lut[tid] = e;
        }
    }
}

// ---------------------------------------------------------------------------
// Main kernel: 512 threads cover one full output row per iteration (one
// float4 per thread), 32 rows per block (rows i = base_i + 4r share i mod 4
// so the staged pos_w slice keeps 16B alignment for every row's LDS.128).
// out[b,i,j] = pos_w[j-i+2048] + ts_w[bucket(ts[b,i+1]-ts[b,j])]
// ---------------------------------------------------------------------------
__device__ __forceinline__ float ts_bias(int tsi1, int tsj, const int4* lut) {
    int dt = tsi1 - tsj;
    int x  = abs(dt);
    x      = max(x, 1);
    float xf = (float)x;                     // exact (x < 2^24)
    int bx   = __float_as_int(xf);
    int idx  = (bx >> 21) - 508;
    int4 L   = lut[idx];
    return __int_as_float(bx >= L.x ? L.z : L.y);
}

#define ROWS_PER_BLK 32
#define OFF 124                              // = 4*(ROWS_PER_BLK-1), keeps poff >= 0

__global__ void __launch_bounds__(512)
k_main(const float* __restrict__ pos_w, float* __restrict__ out) {
    __shared__ __align__(16) float s_pos[2176];   // span 2172 used
    __shared__ __align__(16) int   s_ts[2052];
    __shared__ int4 s_lut[128];

    const int tid = threadIdx.x;
    const int blk = blockIdx.x;              // 1024 blocks
    const int b   = blk >> 6;                // 64 blocks per batch
    const int rb  = blk & 63;
    const int a   = rb & 3;                  // residue i mod 4
    const int tb  = rb >> 2;                 // 0..15
    const int base_i  = a + (tb << 7);       // rows: base_i + 4r, r in [0,32)
    const int s_start = 2048 - base_i - OFF; // pos_w staging origin (>= 1)

    for (int u = tid; u < 2172; u += 512) s_pos[u] = pos_w[s_start + u];
    for (int u = tid; u < 2049; u += 512) s_ts[u] = g_ts32[b * NN + u];
    if (tid < 128) s_lut[tid] = g_lut[tid];
    __syncthreads();

    const int j0 = tid << 2;                 // 0..2044 — one float4 spans the row
    const int4 tsv = *(const int4*)&s_ts[j0];

    #pragma unroll 4
    for (int r = 0; r < ROWS_PER_BLK; ++r) {
        const int i    = base_i + (r << 2);
        const int tsi1 = s_ts[i + 1];
        float* orow = out + (((size_t)(b * NOUT + i)) << 11);
        const int poff = j0 + OFF - (r << 2);   // multiple of 4 -> aligned LDS.128

        float4 pw = *(const float4*)&s_pos[poff];
        float4 o;
        o.x = ts_bias(tsi1, tsv.x, s_lut) + pw.x;
        o.y = ts_bias(tsi1, tsv.y, s_lut) + pw.y;
        o.z = ts_bias(tsi1, tsv.z, s_lut) + pw.z;
        o.w = ts_bias(tsi1, tsv.w, s_lut) + pw.w;
        *(float4*)&orow[j0] = o;
    }
}

extern "C" void kernel_launch(void* const* d_in, const int* in_sizes, int n_in,
                              void* d_out, int out_size) {
    // Identify inputs by element count, not position (defensive).
    const void*  ts_raw = d_in[0];
    const float* posw   = (const float*)d_in[1];
    const float* tsw    = (const float*)d_in[2];
    for (int k = 0; k < n_in; ++k) {
        if (in_sizes[k] == BB * NN)         ts_raw = d_in[k];
        else if (in_sizes[k] == 2 * NN - 1) posw   = (const float*)d_in[k];
        else if (in_sizes[k] == 129)        tsw    = (const float*)d_in[k];
    }
    float* out = (float*)d_out;              // (16, 2048, 2048) f32

    k_prep<<<BB + 1, 256>>>((const int*)ts_raw, tsw);
    k_main<<<1024, 512>>>(posw, out);
}

// round 12
// speedup vs baseline: 1.3468x; 1.0397x over previous
#include <cuda_runtime.h>
#include <math.h>

// Problem constants (fixed shapes per reference)
#define NN   2049          // max_seq_len
#define NOUT 2048          // output rows/cols = N-1
#define BB   16            // batch
// pos_w has 2*NN-1 = 4097 entries, ts_w has 129 entries.

// Device scratch (no allocations allowed in kernel_launch)
__device__ int4 g_lut[128];          // {thr_bits, vlo_bits, vhi_bits, 0} per quarter-octave cell
__device__ int  g_ts32[BB * NN];     // timestamps normalized to int32

// ---------------------------------------------------------------------------
// Genuine libdevice logf (linked from libdevice.bc; immune to fast-math's
// logf->__logf substitution).
// ---------------------------------------------------------------------------
extern "C" __device__ float __nv_logf(float);

// Reference bucketization (verified bit-exact vs the jax reference in R9):
// XLA's algebraic simplifier rewrites divide(log(x), 0.301f) into
// multiply(log(x), rn(1/0.301f)); reciprocal folded once in f32.
__device__ __forceinline__ int bucket_ref(int v, float recip) {
    float r = __nv_logf((float)v);
    float q = __fmul_rn(r, recip);
    return (int)floorf(q);
}

// First INTEGER v in [1, 1e6] with bucket(v) >= k; +inf bits if never reached.
__device__ __forceinline__ int first_int_bits_ge(int k, float recip) {
    int lo = 1;
    int hi = 1000000;
    if (bucket_ref(hi, recip) < k) return 0x7F800000;
    while (lo < hi) {
        int mid = lo + ((hi - lo) >> 1);
        if (bucket_ref(mid, recip) >= k) hi = mid; else lo = mid + 1;
    }
    return __float_as_int((float)lo);
}

// ---------------------------------------------------------------------------
// Fused prologue: ONE launch.
//   blocks 0..15 : normalize timestamps of batch b (dtype-robust int64/int32)
//   block  16    : build the 128-cell threshold LUT
// Detection reads only pair indices < 16392 (first 32784 int words), which
// are inside the buffer under BOTH dtype interpretations.
// ---------------------------------------------------------------------------
__global__ void __launch_bounds__(256)
k_prep(const int* __restrict__ ts_raw, const float* __restrict__ ts_w) {
    const int tid = threadIdx.x;
    const int blk = blockIdx.x;

    if (blk < BB) {
        __shared__ int s_flag;
        if (tid == 0) s_flag = 0;
        __syncthreads();
        int local = 0;
        const int p0 = blk * 1024;           // pairs [p0, p0+1024) all < 16392
        for (int p = p0 + tid; p < p0 + 1024; p += 256)
            local |= ts_raw[2 * p + 1];
        if (local) atomicOr(&s_flag, 1);
        __syncthreads();

        const bool is64 = (s_flag == 0);
        const int base = blk * NN;
        if (is64) {
            for (int u = tid; u < NN; u += 256)
                g_ts32[base + u] = ts_raw[2 * (base + u)];
        } else {
            for (int u = tid; u < NN; u += 256)
                g_ts32[base + u] = ts_raw[base + u];
        }
    } else {
        // --- LUT build (reciprocal hoisted: ONE fdiv per thread total) ---
        const float recip = __fdiv_rn(1.0f, 0.301f);
        __shared__ int Tb[81];
        if (tid <= 80) Tb[tid] = 0x7F800000;
        __syncthreads();
        if (tid >= 1 && tid < 80) Tb[tid] = first_int_bits_ge(tid, recip);
        __syncthreads();

        if (tid < 128) {
            int cellbase = (tid + 508) << 21;
            int cellend  = cellbase + (1 << 21);
            int blo = 0;
            #pragma unroll 1
            for (int k = 1; k < 80; ++k) blo += (Tb[k] <= cellbase) ? 1 : 0;
            int thr = 0x7F800000;
            if (blo + 1 < 80 && Tb[blo + 1] < cellend) thr = Tb[blo + 1];
            int kv0 = min(blo, 128);
            int kv1 = min(blo + 1, 128);
            int4 e;
            e.x = thr;
            e.y = __float_as_int(ts_w[kv0]);
            e.z = __float_as_int(ts_w[kv1]);
            e.w = 0;
            g_lut[tid] = e;
        }
    }
}

// ---------------------------------------------------------------------------
// Main kernel: 512 threads cover one full output row per iteration (one
// float4 per thread), 32 rows per block (rows i = base_i + 4r share i mod 4
// so the staged pos_w slice keeps 16B alignment for every row's LDS.128).
// out[b,i,j] = pos_w[j-i+2048] + ts_w[bucket(ts[b,i+1]-ts[b,j])]
//
// LUT access: within a thread's 4 consecutive j, |dt| spans only ~2k, so all
// four quarter-octave cell indices coincide for ~98% of threads. The branch
// is made warp-uniform with __all_sync: fast warps issue ONE LDS.128 for the
// LUT instead of four, cutting L1 wavefronts (the R11 bottleneck, L1=83%).
// ---------------------------------------------------------------------------
__device__ __forceinline__ int cell_of(int tsi1, int tsj, int& bx) {
    int dt = tsi1 - tsj;
    int x  = max(abs(dt), 1);
    bx = __float_as_int((float)x);           // exact (x < 2^24)
    return (bx >> 21) - 508;
}

#define ROWS_PER_BLK 32
#define OFF 124                              // = 4*(ROWS_PER_BLK-1), keeps poff >= 0

__global__ void __launch_bounds__(512)
k_main(const float* __restrict__ pos_w, float* __restrict__ out) {
    __shared__ __align__(16) float s_pos[2176];   // span 2172 used
    __shared__ __align__(16) int   s_ts[2052];
    __shared__ int4 s_lut[128];

    const int tid = threadIdx.x;
    const int blk = blockIdx.x;              // 1024 blocks
    const int b   = blk >> 6;                // 64 blocks per batch
    const int rb  = blk & 63;
    const int a   = rb & 3;                  // residue i mod 4
    const int tb  = rb >> 2;                 // 0..15
    const int base_i  = a + (tb << 7);       // rows: base_i + 4r, r in [0,32)
    const int s_start = 2048 - base_i - OFF; // pos_w staging origin (>= 1)

    for (int u = tid; u < 2172; u += 512) s_pos[u] = pos_w[s_start + u];
    for (int u = tid; u < 2049; u += 512) s_ts[u] = g_ts32[b * NN + u];
    if (tid < 128) s_lut[tid] = g_lut[tid];
    __syncthreads();

    const int j0 = tid << 2;                 // 0..2044 — one float4 spans the row
    const int4 tsv = *(const int4*)&s_ts[j0];

    #pragma unroll 4
    for (int r = 0; r < ROWS_PER_BLK; ++r) {
        const int i    = base_i + (r << 2);
        const int tsi1 = s_ts[i + 1];
        float* orow = out + (((size_t)(b * NOUT + i)) << 11);
        const int poff = j0 + OFF - (r << 2);   // multiple of 4 -> aligned LDS.128

        int bx0, bx1, bx2, bx3;
        const int c0 = cell_of(tsi1, tsv.x, bx0);
        const int c1 = cell_of(tsi1, tsv.y, bx1);
        const int c2 = cell_of(tsi1, tsv.z, bx2);
        const int c3 = cell_of(tsi1, tsv.w, bx3);

        int4 L0, L1, L2, L3;
        const bool same = (c0 == c1) & (c0 == c2) & (c0 == c3);
        if (__all_sync(0xFFFFFFFFu, same)) {
            L0 = s_lut[c0];                  // one LDS.128 serves all 4
            L1 = L0; L2 = L0; L3 = L0;
        } else {
            L0 = s_lut[c0];
            L1 = s_lut[c1];
            L2 = s_lut[c2];
            L3 = s_lut[c3];
        }

        float4 pw = *(const float4*)&s_pos[poff];
        float4 o;
        o.x = __int_as_float(bx0 >= L0.x ? L0.z : L0.y) + pw.x;
        o.y = __int_as_float(bx1 >= L1.x ? L1.z : L1.y) + pw.y;
        o.z = __int_as_float(bx2 >= L2.x ? L2.z : L2.y) + pw.z;
        o.w = __int_as_float(bx3 >= L3.x ? L3.z : L3.y) + pw.w;

        __stcs((float4*)&orow[j0], o);       // streaming store: write-once data
    }
}

extern "C" void kernel_launch(void* const* d_in, const int* in_sizes, int n_in,
                              void* d_out, int out_size) {
    // Identify inputs by element count, not position (defensive).
    const void*  ts_raw = d_in[0];
    const float* posw   = (const float*)d_in[1];
    const float* tsw    = (const float*)d_in[2];
    for (int k = 0; k < n_in; ++k) {
        if (in_sizes[k] == BB * NN)         ts_raw = d_in[k];
        else if (in_sizes[k] == 2 * NN - 1) posw   = (const float*)d_in[k];
        else if (in_sizes[k] == 129)        tsw    = (const float*)d_in[k];
    }
    float* out = (float*)d_out;              // (16, 2048, 2048) f32

    k_prep<<<BB + 1, 256>>>((const int*)ts_raw, tsw);
    k_main<<<1024, 512>>>(posw, out);
}